// round 1
// baseline (speedup 1.0000x reference)
#include <cuda_runtime.h>
#include <math.h>

#define NPAD 129
#define NT   1024
#define PI_F 3.14159265358979f

// ---------------- device scratch (static: no allocation allowed) -------------
__device__ float2 g_ihat [64  * 16384];    // FFT2(image), bitrev layout, 8 MB
__device__ float2 g_u1hat[1024 * 16384];   // FFT2(|u1|),  bitrev layout, 128 MB
__device__ float  g_psi  [16  * 16384];    // Morlet bank, bitrev layout, 1 MB
__device__ float  g_s0   [64];
__device__ float  g_s1part[1024];          // per (b,j1,l1) sum of |u1|
__device__ float  g_s2part[6144];          // per (b,pair,l1,l2) sum of |field|

__device__ __forceinline__ int brev7(int x) { return (int)(__brev((unsigned)x) >> 25); }

// ---------------- filter bank, stored pre-permuted (bitrev both axes) --------
__global__ void init_psi_kernel() {
    int idx = blockIdx.x * blockDim.x + threadIdx.x;
    if (idx >= 16 * 16384) return;
    int fc = idx & 127;
    int fr = (idx >> 7) & 127;
    int l  = (idx >> 14) & 3;
    int j  = idx >> 16;
    const float w = 2.f * PI_F / 128.f;
    float fx = (float)((fr < 64) ? fr : fr - 128) * w;
    float fy = (float)((fc < 64) ? fc : fc - 128) * w;
    float k0 = (3.f * PI_F / 4.f) / (float)(1 << j);
    float sg = 0.8f * (float)(1 << j);
    float th = PI_F * (float)l / 4.f;
    float k0x = k0 * cosf(th), k0y = k0 * sinf(th);
    float hs = 0.5f * sg * sg;
    float beta = expf(-hs * k0 * k0);
    float gs = expf(-hs * ((fx - k0x) * (fx - k0x) + (fy - k0y) * (fy - k0y)));
    float g0 = expf(-hs * (fx * fx + fy * fy));
    g_psi[((j * 4 + l) << 14) + (brev7(fr) << 7) + brev7(fc)] = gs - beta * g0;
}

// ---------------- in-smem radix-2 FFT stages ---------------------------------
// Forward: DIF, natural in -> bitrev out.  Inverse: DIT, bitrev in -> natural out
// (unscaled; 1/N^2 folded into the pointwise filter multiply).
template <bool INV>
__device__ __forceinline__ void fft_stage(float* re, float* im,
                                          const float* twr, const float* twi,
                                          int s, int dim) {
    int half  = 64 >> s;
    int maskj = half - 1;
    int log2m = 7 - s;
    int shg   = 6 - s;
    for (int idx = threadIdx.x; idx < 8192; idx += NT) {
        int t = idx >> 7;       // butterfly id within a line (0..63)
        int q = idx & 127;      // which line (row or col)
        int j = t & maskj;
        int g = t >> shg;
        int p0 = (g << log2m) + j;
        int p1 = p0 + half;
        int a0, a1;
        if (dim == 0) { a0 = q * NPAD + p0; a1 = q * NPAD + p1; }
        else          { a0 = p0 * NPAD + q; a1 = p1 * NPAD + q; }
        float ar = re[a0], ai = im[a0];
        float br = re[a1], bi = im[a1];
        int   ti = j << s;                  // W_128^{j * 128/m}
        float wr = twr[ti];
        float wi = INV ? -twi[ti] : twi[ti];
        if (!INV) {                         // DIF
            float dr = ar - br, di = ai - bi;
            re[a0] = ar + br;          im[a0] = ai + bi;
            re[a1] = dr * wr - di * wi; im[a1] = dr * wi + di * wr;
        } else {                            // DIT
            float tr = br * wr - bi * wi;
            float tq = br * wi + bi * wr;
            re[a0] = ar + tr; im[a0] = ai + tq;
            re[a1] = ar - tr; im[a1] = ai - tq;
        }
    }
    __syncthreads();
}

__device__ __forceinline__ void fft2d_fwd(float* re, float* im,
                                          const float* twr, const float* twi) {
    for (int dim = 0; dim < 2; dim++)
        for (int s = 0; s < 7; s++)
            fft_stage<false>(re, im, twr, twi, s, dim);
}

__device__ __forceinline__ void fft2d_inv(float* re, float* im,
                                          const float* twr, const float* twi) {
    for (int dim = 0; dim < 2; dim++)
        for (int s = 6; s >= 0; s--)
            fft_stage<true>(re, im, twr, twi, s, dim);
}

#define INIT_TWIDDLES()                                                        \
    do {                                                                       \
        if (threadIdx.x < 64) {                                                \
            float sv, cv;                                                      \
            __sincosf(-2.f * PI_F * (float)threadIdx.x / 128.f, &sv, &cv);     \
            s_twr[threadIdx.x] = cv;                                           \
            s_twi[threadIdx.x] = sv;                                           \
        }                                                                      \
    } while (0)

// ---------------- stage A: i_hat = FFT2(image), s0 ---------------------------
__global__ __launch_bounds__(NT, 1) void kA(const float* __restrict__ img) {
    extern __shared__ float sm[];
    float* re = sm;
    float* im = sm + 128 * NPAD;
    __shared__ float s_twr[64], s_twi[64];
    __shared__ float red[NT];
    int b = blockIdx.x;
    int tid = threadIdx.x;
    INIT_TWIDDLES();

    float local = 0.f;
    for (int idx = tid; idx < 16384; idx += NT) {
        float v = img[b * 16384 + idx];
        int r = idx >> 7, c = idx & 127;
        re[r * NPAD + c] = v;
        im[r * NPAD + c] = 0.f;
        local += v;
    }
    red[tid] = local;
    __syncthreads();
    for (int o = NT / 2; o > 0; o >>= 1) {
        if (tid < o) red[tid] += red[tid + o];
        __syncthreads();
    }
    if (tid == 0) g_s0[b] = red[0] * (1.f / 16384.f);
    __syncthreads();

    fft2d_fwd(re, im, s_twr, s_twi);

    for (int idx = tid; idx < 16384; idx += NT) {
        int r = idx >> 7, c = idx & 127;
        g_ihat[b * 16384 + idx] = make_float2(re[r * NPAD + c], im[r * NPAD + c]);
    }
}

// ---------------- stage B: u1 = |ifft2(i_hat*psi)|, s1 partial, u1_hat -------
__global__ __launch_bounds__(NT, 1) void kB() {
    extern __shared__ float sm[];
    float* re = sm;
    float* im = sm + 128 * NPAD;
    __shared__ float s_twr[64], s_twi[64];
    __shared__ float red[NT];
    int bi = blockIdx.x;              // b*16 + j1*4 + l1
    int b  = bi >> 4;
    int j1 = (bi >> 2) & 3;
    int l1 = bi & 3;
    int tid = threadIdx.x;
    INIT_TWIDDLES();

    const float2* src = g_ihat + (size_t)b * 16384;
    const float*  psi = g_psi + (((size_t)j1 * 4 + l1) << 14);
    const float scale = 1.f / 16384.f;
    for (int idx = tid; idx < 16384; idx += NT) {
        float2 v = src[idx];
        float  p = psi[idx] * scale;
        int r = idx >> 7, c = idx & 127;
        re[r * NPAD + c] = v.x * p;
        im[r * NPAD + c] = v.y * p;
    }
    __syncthreads();

    fft2d_inv(re, im, s_twr, s_twi);

    float local = 0.f;
    for (int idx = tid; idx < 16384; idx += NT) {
        int r = idx >> 7, c = idx & 127;
        float xr = re[r * NPAD + c], xi = im[r * NPAD + c];
        float mag = sqrtf(xr * xr + xi * xi);
        local += mag;
        re[r * NPAD + c] = mag;
        im[r * NPAD + c] = 0.f;
    }
    red[tid] = local;
    __syncthreads();
    for (int o = NT / 2; o > 0; o >>= 1) {
        if (tid < o) red[tid] += red[tid + o];
        __syncthreads();
    }
    if (tid == 0) g_s1part[bi] = red[0];
    __syncthreads();

    if (j1 < 3) {                     // j1 == 3 never consumed by second order
        fft2d_fwd(re, im, s_twr, s_twi);
        float2* dst = g_u1hat + (size_t)bi * 16384;
        for (int idx = tid; idx < 16384; idx += NT) {
            int r = idx >> 7, c = idx & 127;
            dst[idx] = make_float2(re[r * NPAD + c], im[r * NPAD + c]);
        }
    }
}

// ---------------- stage C: s2 partial = sum |ifft2(u1_hat*psi_j2)| -----------
__global__ __launch_bounds__(NT, 1) void kC() {
    extern __shared__ float sm[];
    float* re = sm;
    float* im = sm + 128 * NPAD;
    __shared__ float s_twr[64], s_twi[64];
    __shared__ float red[NT];
    int bi = blockIdx.x;              // b*96 + pair*16 + l1*4 + l2
    int b    = bi / 96;
    int r96  = bi % 96;
    int pair = r96 >> 4;
    int l1   = (r96 >> 2) & 3;
    int l2   = r96 & 3;
    const int J1[6] = {0, 0, 0, 1, 1, 2};
    const int J2[6] = {1, 2, 3, 2, 3, 3};
    int j1 = J1[pair], j2 = J2[pair];
    int tid = threadIdx.x;
    INIT_TWIDDLES();

    const float2* src = g_u1hat + (((size_t)b * 16 + j1 * 4 + l1) << 14);
    const float*  psi = g_psi + (((size_t)j2 * 4 + l2) << 14);
    const float scale = 1.f / 16384.f;
    for (int idx = tid; idx < 16384; idx += NT) {
        float2 v = src[idx];
        float  p = psi[idx] * scale;
        int rr = idx >> 7, c = idx & 127;
        re[rr * NPAD + c] = v.x * p;
        im[rr * NPAD + c] = v.y * p;
    }
    __syncthreads();

    fft2d_inv(re, im, s_twr, s_twi);

    float local = 0.f;
    for (int idx = tid; idx < 16384; idx += NT) {
        int rr = idx >> 7, c = idx & 127;
        float xr = re[rr * NPAD + c], xi = im[rr * NPAD + c];
        local += sqrtf(xr * xr + xi * xi);
    }
    red[tid] = local;
    __syncthreads();
    for (int o = NT / 2; o > 0; o >>= 1) {
        if (tid < o) red[tid] += red[tid + o];
        __syncthreads();
    }
    if (tid == 0) g_s2part[bi] = red[0];
}

// ---------------- stage D: deterministic reduce + MLP ------------------------
__global__ void kD(const float* __restrict__ fc1w, const float* __restrict__ fc1b,
                   const float* __restrict__ fc2w, const float* __restrict__ fc2b,
                   float* __restrict__ out) {
    int b = threadIdx.x;
    if (b >= 64) return;
    float s[11];
    s[0] = g_s0[b];
    for (int j = 0; j < 4; j++) {
        float acc = 0.f;
        for (int l = 0; l < 4; l++) acc += g_s1part[b * 16 + j * 4 + l];
        s[1 + j] = acc * (1.f / (4.f * 16384.f));
    }
    for (int p = 0; p < 6; p++) {
        float acc = 0.f;
        for (int k = 0; k < 16; k++) acc += g_s2part[b * 96 + p * 16 + k];
        s[5 + p] = acc * (1.f / (16.f * 16384.f));
    }
    float h[4];
    for (int i = 0; i < 4; i++) {
        float a = fc1b[i];
        for (int t = 0; t < 11; t++) a += fc1w[i * 11 + t] * s[t];
        h[i] = fmaxf(a, 0.f);
    }
    for (int k = 0; k < 10; k++) {
        float a = fc2b[k];
        for (int i = 0; i < 4; i++) a += fc2w[k * 4 + i] * h[i];
        out[b * 10 + k] = 1.f / (1.f + expf(-a));
    }
}

// ---------------- launch -----------------------------------------------------
extern "C" void kernel_launch(void* const* d_in, const int* in_sizes, int n_in,
                              void* d_out, int out_size) {
    const float* img  = (const float*)d_in[0];
    const float* fc1w = (const float*)d_in[1];
    const float* fc1b = (const float*)d_in[2];
    const float* fc2w = (const float*)d_in[3];
    const float* fc2b = (const float*)d_in[4];
    float* out = (float*)d_out;

    const size_t smem = 2 * 128 * NPAD * sizeof(float);   // 132096 bytes
    cudaFuncSetAttribute(kA, cudaFuncAttributeMaxDynamicSharedMemorySize, (int)smem);
    cudaFuncSetAttribute(kB, cudaFuncAttributeMaxDynamicSharedMemorySize, (int)smem);
    cudaFuncSetAttribute(kC, cudaFuncAttributeMaxDynamicSharedMemorySize, (int)smem);

    init_psi_kernel<<<256, 1024>>>();
    kA<<<64, NT, smem>>>(img);
    kB<<<1024, NT, smem>>>();
    kC<<<6144, NT, smem>>>();
    kD<<<1, 64>>>(fc1w, fc1b, fc2w, fc2b, out);
}

// round 5
// speedup vs baseline: 1.8122x; 1.8122x over previous
#include <cuda_runtime.h>
#include <math.h>

#define NPAD 129
#define NT   1024
#define PI_F 3.14159265358979f

// ---------------- device scratch (static: no allocation allowed) -------------
__device__ float2 g_ihat [64  * 16384];    // FFT2(image), digit-rev layout
__device__ float2 g_u1hat[1024 * 16384];   // FFT2(|u1|),  digit-rev layout
__device__ float  g_psi  [16  * 16384];    // Morlet bank, digit-rev layout
__device__ float  g_s0   [64];
__device__ float  g_s1part[1024];
__device__ float  g_s2part[6144];

// digit-reversal for radix [8,4,4] DIF: freq f -> storage position
__device__ __forceinline__ int dperm(int f) {
    return ((f & 7) << 4) | (((f >> 3) & 3) << 2) | (f >> 5);
}

// ---------------- filter bank, stored pre-permuted ---------------------------
__global__ void init_psi_kernel() {
    int idx = blockIdx.x * blockDim.x + threadIdx.x;
    if (idx >= 16 * 16384) return;
    int fc = idx & 127;
    int fr = (idx >> 7) & 127;
    int l  = (idx >> 14) & 3;
    int j  = idx >> 16;
    const float w = 2.f * PI_F / 128.f;
    float fx = (float)((fr < 64) ? fr : fr - 128) * w;
    float fy = (float)((fc < 64) ? fc : fc - 128) * w;
    float k0 = (3.f * PI_F / 4.f) / (float)(1 << j);
    float sg = 0.8f * (float)(1 << j);
    float th = PI_F * (float)l / 4.f;
    float k0x = k0 * cosf(th), k0y = k0 * sinf(th);
    float hs = 0.5f * sg * sg;
    float beta = expf(-hs * k0 * k0);
    float gs = expf(-hs * ((fx - k0x) * (fx - k0x) + (fy - k0y) * (fy - k0y)));
    float g0 = expf(-hs * (fx * fx + fy * fy));
    g_psi[((j * 4 + l) << 14) + (dperm(fr) << 7) + dperm(fc)] = gs - beta * g0;
}

// ---------------- register butterflies (interleaved complex) -----------------
template <bool INV>
__device__ __forceinline__ void bfly4(float2* x) {
    float t0r = x[0].x + x[2].x, t0i = x[0].y + x[2].y;
    float t1r = x[0].x - x[2].x, t1i = x[0].y - x[2].y;
    float t2r = x[1].x + x[3].x, t2i = x[1].y + x[3].y;
    float t3r = x[1].x - x[3].x, t3i = x[1].y - x[3].y;
    x[0].x = t0r + t2r; x[0].y = t0i + t2i;
    x[2].x = t0r - t2r; x[2].y = t0i - t2i;
    if (!INV) {
        x[1].x = t1r + t3i; x[1].y = t1i - t3r;
        x[3].x = t1r - t3i; x[3].y = t1i + t3r;
    } else {
        x[1].x = t1r - t3i; x[1].y = t1i + t3r;
        x[3].x = t1r + t3i; x[3].y = t1i - t3r;
    }
}

template <bool INV>
__device__ __forceinline__ void bfly8(float2* x) {
    const float C = 0.70710678118654752f;
    // even DFT4 (x0,x2,x4,x6)
    float t0r = x[0].x + x[4].x, t0i = x[0].y + x[4].y;
    float t1r = x[0].x - x[4].x, t1i = x[0].y - x[4].y;
    float t2r = x[2].x + x[6].x, t2i = x[2].y + x[6].y;
    float t3r = x[2].x - x[6].x, t3i = x[2].y - x[6].y;
    float e0r = t0r + t2r, e0i = t0i + t2i;
    float e2r = t0r - t2r, e2i = t0i - t2i;
    float e1r, e1i, e3r, e3i;
    if (!INV) { e1r = t1r + t3i; e1i = t1i - t3r; e3r = t1r - t3i; e3i = t1i + t3r; }
    else      { e1r = t1r - t3i; e1i = t1i + t3r; e3r = t1r + t3i; e3i = t1i - t3r; }
    // odd DFT4 (x1,x3,x5,x7)
    float u0r = x[1].x + x[5].x, u0i = x[1].y + x[5].y;
    float u1r = x[1].x - x[5].x, u1i = x[1].y - x[5].y;
    float u2r = x[3].x + x[7].x, u2i = x[3].y + x[7].y;
    float u3r = x[3].x - x[7].x, u3i = x[3].y - x[7].y;
    float o0r = u0r + u2r, o0i = u0i + u2i;
    float o2r = u0r - u2r, o2i = u0i - u2i;
    float o1r, o1i, o3r, o3i;
    if (!INV) { o1r = u1r + u3i; o1i = u1i - u3r; o3r = u1r - u3i; o3i = u1i + u3r; }
    else      { o1r = u1r - u3i; o1i = u1i + u3r; o3r = u1r + u3i; o3i = u1i - u3r; }
    // W8^k * o_k
    float w1r, w1i, w2r, w2i, w3r, w3i;
    if (!INV) {
        w1r = C * (o1r + o1i); w1i = C * (o1i - o1r);
        w2r = o2i;             w2i = -o2r;
        w3r = C * (o3i - o3r); w3i = -C * (o3r + o3i);
    } else {
        w1r = C * (o1r - o1i); w1i = C * (o1i + o1r);
        w2r = -o2i;            w2i = o2r;
        w3r = -C * (o3r + o3i); w3i = C * (o3r - o3i);
    }
    x[0].x = e0r + o0r; x[0].y = e0i + o0i;
    x[1].x = e1r + w1r; x[1].y = e1i + w1i;
    x[2].x = e2r + w2r; x[2].y = e2i + w2i;
    x[3].x = e3r + w3r; x[3].y = e3i + w3i;
    x[4].x = e0r - o0r; x[4].y = e0i - o0i;
    x[5].x = e1r - w1r; x[5].y = e1i - w1i;
    x[6].x = e2r - w2r; x[6].y = e2i - w2i;
    x[7].x = e3r - w3r; x[7].y = e3i - w3i;
}

// ---------------- mixed-radix [8,4,4] smem stages ----------------------------
// fwd: DIF natural -> digit-reversed.  inv: exact stage-inverse, reverse order.
// sc: interleaved complex plane, row stride NPAD float2.
template <bool INV, int DIM>
__device__ __forceinline__ void r8_stage(float2* sc,
                                         const float* twr, const float* twi) {
    for (int idx = threadIdx.x; idx < 2048; idx += NT) {
        int q = idx & 127, j = idx >> 7;           // j in [0,16)
        int base = (DIM == 0) ? q * NPAD + j : j * NPAD + q;
        int step = (DIM == 0) ? 16 : 16 * NPAD;
        float2 x[8];
#pragma unroll
        for (int k = 0; k < 8; k++) x[k] = sc[base + k * step];
        if (INV) {
#pragma unroll
            for (int k = 1; k < 8; k++) {
                int t = j * k;
                float wr = twr[t], wi = -twi[t];
                float a = x[k].x, b = x[k].y;
                x[k].x = a * wr - b * wi; x[k].y = a * wi + b * wr;
            }
        }
        bfly8<INV>(x);
        if (!INV) {
#pragma unroll
            for (int k = 1; k < 8; k++) {
                int t = j * k;
                float wr = twr[t], wi = twi[t];
                float a = x[k].x, b = x[k].y;
                x[k].x = a * wr - b * wi; x[k].y = a * wi + b * wr;
            }
        }
#pragma unroll
        for (int k = 0; k < 8; k++) sc[base + k * step] = x[k];
    }
    __syncthreads();
}

template <bool INV, int DIM>
__device__ __forceinline__ void r4mid_stage(float2* sc,
                                            const float* twr, const float* twi) {
    for (int idx = threadIdx.x; idx < 4096; idx += NT) {
        int q = idx & 127, t = idx >> 7;           // t in [0,32)
        int g = t >> 2, j = t & 3;
        int p = (g << 4) + j;
        int base = (DIM == 0) ? q * NPAD + p : p * NPAD + q;
        int step = (DIM == 0) ? 4 : 4 * NPAD;
        float2 x[4];
#pragma unroll
        for (int k = 0; k < 4; k++) x[k] = sc[base + k * step];
        if (INV) {
#pragma unroll
            for (int k = 1; k < 4; k++) {
                int ti = 8 * j * k;
                float wr = twr[ti], wi = -twi[ti];
                float a = x[k].x, b = x[k].y;
                x[k].x = a * wr - b * wi; x[k].y = a * wi + b * wr;
            }
        }
        bfly4<INV>(x);
        if (!INV) {
#pragma unroll
            for (int k = 1; k < 4; k++) {
                int ti = 8 * j * k;
                float wr = twr[ti], wi = twi[ti];
                float a = x[k].x, b = x[k].y;
                x[k].x = a * wr - b * wi; x[k].y = a * wi + b * wr;
            }
        }
#pragma unroll
        for (int k = 0; k < 4; k++) sc[base + k * step] = x[k];
    }
    __syncthreads();
}

template <bool INV, int DIM>
__device__ __forceinline__ void r4last_stage(float2* sc) {
    for (int idx = threadIdx.x; idx < 4096; idx += NT) {
        int q = idx & 127, g = idx >> 7;           // g in [0,32)
        int p = g << 2;
        int base = (DIM == 0) ? q * NPAD + p : p * NPAD + q;
        int step = (DIM == 0) ? 1 : NPAD;
        float2 x[4];
#pragma unroll
        for (int k = 0; k < 4; k++) x[k] = sc[base + k * step];
        bfly4<INV>(x);
#pragma unroll
        for (int k = 0; k < 4; k++) sc[base + k * step] = x[k];
    }
    __syncthreads();
}

__device__ __forceinline__ void fft2d_fwd(float2* sc,
                                          const float* twr, const float* twi) {
    r8_stage<false, 0>(sc, twr, twi);
    r4mid_stage<false, 0>(sc, twr, twi);
    r4last_stage<false, 0>(sc);
    r8_stage<false, 1>(sc, twr, twi);
    r4mid_stage<false, 1>(sc, twr, twi);
    r4last_stage<false, 1>(sc);
}

__device__ __forceinline__ void fft2d_inv(float2* sc,
                                          const float* twr, const float* twi) {
    r4last_stage<true, 0>(sc);
    r4mid_stage<true, 0>(sc, twr, twi);
    r8_stage<true, 0>(sc, twr, twi);
    r4last_stage<true, 1>(sc);
    r4mid_stage<true, 1>(sc, twr, twi);
    r8_stage<true, 1>(sc, twr, twi);
}

#define INIT_TWIDDLES()                                                        \
    do {                                                                       \
        if (threadIdx.x < 128) {                                               \
            float sv, cv;                                                      \
            __sincosf(-2.f * PI_F * (float)threadIdx.x / 128.f, &sv, &cv);     \
            s_twr[threadIdx.x] = cv;                                           \
            s_twi[threadIdx.x] = sv;                                           \
        }                                                                      \
    } while (0)

// warp-shuffle block reduction (deterministic); result valid in tid 0
__device__ __forceinline__ float block_sum(float v, float* red) {
#pragma unroll
    for (int o = 16; o; o >>= 1) v += __shfl_xor_sync(0xffffffffu, v, o);
    if ((threadIdx.x & 31) == 0) red[threadIdx.x >> 5] = v;
    __syncthreads();
    float s = 0.f;
    if (threadIdx.x < 32) {
        s = red[threadIdx.x];
#pragma unroll
        for (int o = 16; o; o >>= 1) s += __shfl_xor_sync(0xffffffffu, s, o);
    }
    return s;
}

// ---------------- stage A: i_hat = FFT2(image), s0 ---------------------------
__global__ __launch_bounds__(NT, 1) void kA(const float* __restrict__ img) {
    extern __shared__ float2 sc[];
    __shared__ float s_twr[128], s_twi[128];
    __shared__ float red[32];
    int b = blockIdx.x;
    int tid = threadIdx.x;
    INIT_TWIDDLES();

    float local = 0.f;
    for (int idx = tid; idx < 16384; idx += NT) {
        float v = img[b * 16384 + idx];
        int r = idx >> 7, c = idx & 127;
        sc[r * NPAD + c] = make_float2(v, 0.f);
        local += v;
    }
    float s = block_sum(local, red);   // includes the barrier before FFT
    if (tid == 0) g_s0[b] = s * (1.f / 16384.f);

    fft2d_fwd(sc, s_twr, s_twi);

    for (int idx = tid; idx < 16384; idx += NT) {
        int r = idx >> 7, c = idx & 127;
        g_ihat[b * 16384 + idx] = sc[r * NPAD + c];
    }
}

// ---------------- stage B: u1 = |ifft2(i_hat*psi)|, s1 partial, u1_hat -------
__global__ __launch_bounds__(NT, 1) void kB() {
    extern __shared__ float2 sc[];
    __shared__ float s_twr[128], s_twi[128];
    __shared__ float red[32];
    int bi = blockIdx.x;              // b*16 + j1*4 + l1
    int b  = bi >> 4;
    int j1 = (bi >> 2) & 3;
    int l1 = bi & 3;
    int tid = threadIdx.x;
    INIT_TWIDDLES();

    const float2* src = g_ihat + (size_t)b * 16384;
    const float*  psi = g_psi + (((size_t)j1 * 4 + l1) << 14);
    const float scale = 1.f / 16384.f;
    for (int idx = tid; idx < 16384; idx += NT) {
        float2 v = src[idx];
        float  p = psi[idx] * scale;
        int r = idx >> 7, c = idx & 127;
        sc[r * NPAD + c] = make_float2(v.x * p, v.y * p);
    }
    __syncthreads();

    fft2d_inv(sc, s_twr, s_twi);

    float local = 0.f;
    for (int idx = tid; idx < 16384; idx += NT) {
        int r = idx >> 7, c = idx & 127;
        float2 x = sc[r * NPAD + c];
        float mag = sqrtf(x.x * x.x + x.y * x.y);
        local += mag;
        sc[r * NPAD + c] = make_float2(mag, 0.f);
    }
    float s = block_sum(local, red);   // barrier covers mag writes
    if (tid == 0) g_s1part[bi] = s;

    if (j1 < 3) {                     // j1 == 3 never consumed by second order
        fft2d_fwd(sc, s_twr, s_twi);
        float2* dst = g_u1hat + (size_t)bi * 16384;
        for (int idx = tid; idx < 16384; idx += NT) {
            int r = idx >> 7, c = idx & 127;
            dst[idx] = sc[r * NPAD + c];
        }
    }
}

// ---------------- stage C: s2 partial = sum |ifft2(u1_hat*psi_j2)| -----------
__global__ __launch_bounds__(NT, 1) void kC() {
    extern __shared__ float2 sc[];
    __shared__ float s_twr[128], s_twi[128];
    __shared__ float red[32];
    int bi = blockIdx.x;              // b*96 + pair*16 + l1*4 + l2
    int b    = bi / 96;
    int r96  = bi % 96;
    int pair = r96 >> 4;
    int l1   = (r96 >> 2) & 3;
    int l2   = r96 & 3;
    const int J1[6] = {0, 0, 0, 1, 1, 2};
    const int J2[6] = {1, 2, 3, 2, 3, 3};
    int j1 = J1[pair], j2 = J2[pair];
    int tid = threadIdx.x;
    INIT_TWIDDLES();

    const float2* src = g_u1hat + (((size_t)b * 16 + j1 * 4 + l1) << 14);
    const float*  psi = g_psi + (((size_t)j2 * 4 + l2) << 14);
    const float scale = 1.f / 16384.f;
    for (int idx = tid; idx < 16384; idx += NT) {
        float2 v = src[idx];
        float  p = psi[idx] * scale;
        int rr = idx >> 7, c = idx & 127;
        sc[rr * NPAD + c] = make_float2(v.x * p, v.y * p);
    }
    __syncthreads();

    fft2d_inv(sc, s_twr, s_twi);

    float local = 0.f;
    for (int idx = tid; idx < 16384; idx += NT) {
        int rr = idx >> 7, c = idx & 127;
        float2 x = sc[rr * NPAD + c];
        local += sqrtf(x.x * x.x + x.y * x.y);
    }
    float s = block_sum(local, red);
    if (tid == 0) g_s2part[bi] = s;
}

// ---------------- stage D: deterministic reduce + MLP ------------------------
__global__ void kD(const float* __restrict__ fc1w, const float* __restrict__ fc1b,
                   const float* __restrict__ fc2w, const float* __restrict__ fc2b,
                   float* __restrict__ out) {
    int b = threadIdx.x;
    if (b >= 64) return;
    float s[11];
    s[0] = g_s0[b];
    for (int j = 0; j < 4; j++) {
        float acc = 0.f;
        for (int l = 0; l < 4; l++) acc += g_s1part[b * 16 + j * 4 + l];
        s[1 + j] = acc * (1.f / (4.f * 16384.f));
    }
    for (int p = 0; p < 6; p++) {
        float acc = 0.f;
        for (int k = 0; k < 16; k++) acc += g_s2part[b * 96 + p * 16 + k];
        s[5 + p] = acc * (1.f / (16.f * 16384.f));
    }
    float h[4];
    for (int i = 0; i < 4; i++) {
        float a = fc1b[i];
        for (int t = 0; t < 11; t++) a += fc1w[i * 11 + t] * s[t];
        h[i] = fmaxf(a, 0.f);
    }
    for (int k = 0; k < 10; k++) {
        float a = fc2b[k];
        for (int i = 0; i < 4; i++) a += fc2w[k * 4 + i] * h[i];
        out[b * 10 + k] = 1.f / (1.f + expf(-a));
    }
}

// ---------------- launch -----------------------------------------------------
extern "C" void kernel_launch(void* const* d_in, const int* in_sizes, int n_in,
                              void* d_out, int out_size) {
    const float* img  = (const float*)d_in[0];
    const float* fc1w = (const float*)d_in[1];
    const float* fc1b = (const float*)d_in[2];
    const float* fc2w = (const float*)d_in[3];
    const float* fc2b = (const float*)d_in[4];
    float* out = (float*)d_out;

    const size_t smem = 128 * NPAD * sizeof(float2);   // 132096 bytes
    cudaFuncSetAttribute(kA, cudaFuncAttributeMaxDynamicSharedMemorySize, (int)smem);
    cudaFuncSetAttribute(kB, cudaFuncAttributeMaxDynamicSharedMemorySize, (int)smem);
    cudaFuncSetAttribute(kC, cudaFuncAttributeMaxDynamicSharedMemorySize, (int)smem);

    init_psi_kernel<<<256, 1024>>>();
    kA<<<64, NT, smem>>>(img);
    kB<<<1024, NT, smem>>>();
    kC<<<6144, NT, smem>>>();
    kD<<<1, 64>>>(fc1w, fc1b, fc2w, fc2b, out);
}

// round 6
// speedup vs baseline: 2.1421x; 1.1820x over previous
#include <cuda_runtime.h>
#include <math.h>

#define NPAD 129
#define NT   512
#define PI_F 3.14159265358979f

// ---------------- device scratch (static: no allocation allowed) -------------
__device__ float2 g_ihat [64  * 16384];    // FFT2(image), digit-rev layout
__device__ float2 g_u1hat[1024 * 16384];   // FFT2(|u1|),  digit-rev layout
__device__ float  g_psi  [16  * 16384];    // Morlet bank, digit-rev layout
__device__ float  g_s0   [64];
__device__ float  g_s1part[1024];
__device__ float  g_s2part[6144];

// digit-reversal for radix [8,4,4] DIF: freq f -> storage position
__device__ __forceinline__ int dperm(int f) {
    return ((f & 7) << 4) | (((f >> 3) & 3) << 2) | (f >> 5);
}

// ---------------- filter bank, stored pre-permuted ---------------------------
__global__ void init_psi_kernel() {
    int idx = blockIdx.x * blockDim.x + threadIdx.x;
    if (idx >= 16 * 16384) return;
    int fc = idx & 127;
    int fr = (idx >> 7) & 127;
    int l  = (idx >> 14) & 3;
    int j  = idx >> 16;
    const float w = 2.f * PI_F / 128.f;
    float fx = (float)((fr < 64) ? fr : fr - 128) * w;
    float fy = (float)((fc < 64) ? fc : fc - 128) * w;
    float k0 = (3.f * PI_F / 4.f) / (float)(1 << j);
    float sg = 0.8f * (float)(1 << j);
    float th = PI_F * (float)l / 4.f;
    float k0x = k0 * cosf(th), k0y = k0 * sinf(th);
    float hs = 0.5f * sg * sg;
    float beta = expf(-hs * k0 * k0);
    float gs = expf(-hs * ((fx - k0x) * (fx - k0x) + (fy - k0y) * (fy - k0y)));
    float g0 = expf(-hs * (fx * fx + fy * fy));
    g_psi[((j * 4 + l) << 14) + (dperm(fr) << 7) + dperm(fc)] = gs - beta * g0;
}

// ---------------- register butterflies (interleaved complex) -----------------
template <bool INV>
__device__ __forceinline__ void bfly4(float2* x) {
    float t0r = x[0].x + x[2].x, t0i = x[0].y + x[2].y;
    float t1r = x[0].x - x[2].x, t1i = x[0].y - x[2].y;
    float t2r = x[1].x + x[3].x, t2i = x[1].y + x[3].y;
    float t3r = x[1].x - x[3].x, t3i = x[1].y - x[3].y;
    x[0].x = t0r + t2r; x[0].y = t0i + t2i;
    x[2].x = t0r - t2r; x[2].y = t0i - t2i;
    if (!INV) {
        x[1].x = t1r + t3i; x[1].y = t1i - t3r;
        x[3].x = t1r - t3i; x[3].y = t1i + t3r;
    } else {
        x[1].x = t1r - t3i; x[1].y = t1i + t3r;
        x[3].x = t1r + t3i; x[3].y = t1i - t3r;
    }
}

template <bool INV>
__device__ __forceinline__ void bfly8(float2* x) {
    const float C = 0.70710678118654752f;
    float t0r = x[0].x + x[4].x, t0i = x[0].y + x[4].y;
    float t1r = x[0].x - x[4].x, t1i = x[0].y - x[4].y;
    float t2r = x[2].x + x[6].x, t2i = x[2].y + x[6].y;
    float t3r = x[2].x - x[6].x, t3i = x[2].y - x[6].y;
    float e0r = t0r + t2r, e0i = t0i + t2i;
    float e2r = t0r - t2r, e2i = t0i - t2i;
    float e1r, e1i, e3r, e3i;
    if (!INV) { e1r = t1r + t3i; e1i = t1i - t3r; e3r = t1r - t3i; e3i = t1i + t3r; }
    else      { e1r = t1r - t3i; e1i = t1i + t3r; e3r = t1r + t3i; e3i = t1i - t3r; }
    float u0r = x[1].x + x[5].x, u0i = x[1].y + x[5].y;
    float u1r = x[1].x - x[5].x, u1i = x[1].y - x[5].y;
    float u2r = x[3].x + x[7].x, u2i = x[3].y + x[7].y;
    float u3r = x[3].x - x[7].x, u3i = x[3].y - x[7].y;
    float o0r = u0r + u2r, o0i = u0i + u2i;
    float o2r = u0r - u2r, o2i = u0i - u2i;
    float o1r, o1i, o3r, o3i;
    if (!INV) { o1r = u1r + u3i; o1i = u1i - u3r; o3r = u1r - u3i; o3i = u1i + u3r; }
    else      { o1r = u1r - u3i; o1i = u1i + u3r; o3r = u1r + u3i; o3i = u1i - u3r; }
    float w1r, w1i, w2r, w2i, w3r, w3i;
    if (!INV) {
        w1r = C * (o1r + o1i); w1i = C * (o1i - o1r);
        w2r = o2i;             w2i = -o2r;
        w3r = C * (o3i - o3r); w3i = -C * (o3r + o3i);
    } else {
        w1r = C * (o1r - o1i); w1i = C * (o1i + o1r);
        w2r = -o2i;            w2i = o2r;
        w3r = -C * (o3r + o3i); w3i = C * (o3r - o3i);
    }
    x[0].x = e0r + o0r; x[0].y = e0i + o0i;
    x[1].x = e1r + w1r; x[1].y = e1i + w1i;
    x[2].x = e2r + w2r; x[2].y = e2i + w2i;
    x[3].x = e3r + w3r; x[3].y = e3i + w3i;
    x[4].x = e0r - o0r; x[4].y = e0i - o0i;
    x[5].x = e1r - w1r; x[5].y = e1i - w1i;
    x[6].x = e2r - w2r; x[6].y = e2i - w2i;
    x[7].x = e3r - w3r; x[7].y = e3i - w3i;
}

// ---- combined [r4-mid (stride4) + r4-last (stride1)] on 16 register points --
// fwd: mid (bfly then W^{8jk}) over m=j+4k, then last over m=4a+i.
// inv: exact inverse: last^-1 (bfly4<true>), then mid^-1 (conj W, bfly4<true>).
template <bool INV>
__device__ __forceinline__ void comb_regs(float2* x, const float* twr, const float* twi) {
    if (!INV) {
#pragma unroll
        for (int j = 0; j < 4; j++) {
            float2 y[4];
#pragma unroll
            for (int k = 0; k < 4; k++) y[k] = x[j + 4 * k];
            bfly4<false>(y);
#pragma unroll
            for (int k = 1; k < 4; k++) {
                int ti = 8 * j * k;
                float wr = twr[ti], wi = twi[ti];
                float a = y[k].x, b = y[k].y;
                y[k].x = a * wr - b * wi; y[k].y = a * wi + b * wr;
            }
#pragma unroll
            for (int k = 0; k < 4; k++) x[j + 4 * k] = y[k];
        }
#pragma unroll
        for (int a = 0; a < 4; a++) bfly4<false>(&x[4 * a]);
    } else {
#pragma unroll
        for (int a = 0; a < 4; a++) bfly4<true>(&x[4 * a]);
#pragma unroll
        for (int j = 0; j < 4; j++) {
            float2 y[4];
#pragma unroll
            for (int k = 0; k < 4; k++) y[k] = x[j + 4 * k];
#pragma unroll
            for (int k = 1; k < 4; k++) {
                int ti = 8 * j * k;
                float wr = twr[ti], wi = -twi[ti];
                float a = y[k].x, b = y[k].y;
                y[k].x = a * wr - b * wi; y[k].y = a * wi + b * wr;
            }
            bfly4<true>(y);
#pragma unroll
            for (int k = 0; k < 4; k++) x[j + 4 * k] = y[k];
        }
    }
}

// ---------------- smem passes ------------------------------------------------
template <bool INV, int DIM>
__device__ __forceinline__ void comb_stage(float2* sc, const float* twr, const float* twi) {
    for (int idx = threadIdx.x; idx < 1024; idx += NT) {
        int q = idx & 127, g = idx >> 7;            // g in [0,8)
        int base = (DIM == 0) ? q * NPAD + (g << 4) : (g << 4) * NPAD + q;
        int step = (DIM == 0) ? 1 : NPAD;
        float2 x[16];
#pragma unroll
        for (int m = 0; m < 16; m++) x[m] = sc[base + m * step];
        comb_regs<INV>(x, twr, twi);
#pragma unroll
        for (int m = 0; m < 16; m++) sc[base + m * step] = x[m];
    }
    __syncthreads();
}

template <bool INV, int DIM>
__device__ __forceinline__ void r8_stage(float2* sc, const float* twr, const float* twi) {
    for (int idx = threadIdx.x; idx < 2048; idx += NT) {
        int q = idx & 127, j = idx >> 7;            // j in [0,16)
        int base = (DIM == 0) ? q * NPAD + j : j * NPAD + q;
        int step = (DIM == 0) ? 16 : 16 * NPAD;
        float2 x[8];
#pragma unroll
        for (int k = 0; k < 8; k++) x[k] = sc[base + k * step];
        if (INV) {
#pragma unroll
            for (int k = 1; k < 8; k++) {
                int t = j * k;
                float wr = twr[t], wi = -twi[t];
                float a = x[k].x, b = x[k].y;
                x[k].x = a * wr - b * wi; x[k].y = a * wi + b * wr;
            }
        }
        bfly8<INV>(x);
        if (!INV) {
#pragma unroll
            for (int k = 1; k < 8; k++) {
                int t = j * k;
                float wr = twr[t], wi = twi[t];
                float a = x[k].x, b = x[k].y;
                x[k].x = a * wr - b * wi; x[k].y = a * wi + b * wr;
            }
        }
#pragma unroll
        for (int k = 0; k < 8; k++) sc[base + k * step] = x[k];
    }
    __syncthreads();
}

// fused: (gmem src * psi * scale) -> combined inverse dim0 -> smem
__device__ __forceinline__ void pass_load_inv0(float2* sc, const float2* __restrict__ src,
                                               const float* __restrict__ psi,
                                               const float* twr, const float* twi) {
    const float scale = 1.f / 16384.f;
    for (int idx = threadIdx.x; idx < 1024; idx += NT) {
        int rr = idx & 127, g = idx >> 7;
        int gbase = rr * 128 + (g << 4);
        const float4* s4 = reinterpret_cast<const float4*>(src + gbase);  // 128B aligned
        const float4* p4 = reinterpret_cast<const float4*>(psi + gbase);  // 64B aligned
        float2 x[16];
#pragma unroll
        for (int m8 = 0; m8 < 4; m8++) {
            float4 p = p4[m8];
            float4 v0 = s4[m8 * 2], v1 = s4[m8 * 2 + 1];
            float pa = p.x * scale, pb = p.y * scale, pc = p.z * scale, pd = p.w * scale;
            x[m8 * 4 + 0] = make_float2(v0.x * pa, v0.y * pa);
            x[m8 * 4 + 1] = make_float2(v0.z * pb, v0.w * pb);
            x[m8 * 4 + 2] = make_float2(v1.x * pc, v1.y * pc);
            x[m8 * 4 + 3] = make_float2(v1.z * pd, v1.w * pd);
        }
        comb_regs<true>(x, twr, twi);
        int base = rr * NPAD + (g << 4);
#pragma unroll
        for (int m = 0; m < 16; m++) sc[base + m] = x[m];
    }
    __syncthreads();
}

// final inverse r8 on dim1 + |.|; optionally write mag back (re=mag, im=0)
template <bool WRITE>
__device__ __forceinline__ float pass_inv1_r8_mag(float2* sc, const float* twr, const float* twi) {
    float local = 0.f;
    for (int idx = threadIdx.x; idx < 2048; idx += NT) {
        int q = idx & 127, j = idx >> 7;
        int base = j * NPAD + q;
        int step = 16 * NPAD;
        float2 x[8];
#pragma unroll
        for (int k = 0; k < 8; k++) x[k] = sc[base + k * step];
#pragma unroll
        for (int k = 1; k < 8; k++) {
            int t = j * k;
            float wr = twr[t], wi = -twi[t];
            float a = x[k].x, b = x[k].y;
            x[k].x = a * wr - b * wi; x[k].y = a * wi + b * wr;
        }
        bfly8<true>(x);
#pragma unroll
        for (int k = 0; k < 8; k++) {
            float mag = sqrtf(x[k].x * x[k].x + x[k].y * x[k].y);
            local += mag;
            if (WRITE) sc[base + k * step] = make_float2(mag, 0.f);
        }
    }
    __syncthreads();
    return local;
}

// final forward combined dim1 -> gmem store (coalesced per leg)
__device__ __forceinline__ void pass_fwd1_store(float2* sc, float2* __restrict__ dst,
                                                const float* twr, const float* twi) {
    for (int idx = threadIdx.x; idx < 1024; idx += NT) {
        int q = idx & 127, g = idx >> 7;
        int base = (g << 4) * NPAD + q;
        float2 x[16];
#pragma unroll
        for (int m = 0; m < 16; m++) x[m] = sc[base + m * NPAD];
        comb_regs<false>(x, twr, twi);
#pragma unroll
        for (int m = 0; m < 16; m++) dst[((g << 4) + m) * 128 + q] = x[m];
    }
}

#define INIT_TWIDDLES()                                                        \
    do {                                                                       \
        if (threadIdx.x < 128) {                                               \
            float sv, cv;                                                      \
            __sincosf(-2.f * PI_F * (float)threadIdx.x / 128.f, &sv, &cv);     \
            s_twr[threadIdx.x] = cv;                                           \
            s_twi[threadIdx.x] = sv;                                           \
        }                                                                      \
    } while (0)

// warp-shuffle block reduction (deterministic); result valid in tid 0
__device__ __forceinline__ float block_sum(float v, float* red) {
#pragma unroll
    for (int o = 16; o; o >>= 1) v += __shfl_xor_sync(0xffffffffu, v, o);
    if ((threadIdx.x & 31) == 0) red[threadIdx.x >> 5] = v;
    __syncthreads();
    float s = 0.f;
    if (threadIdx.x < 32) {
        s = (threadIdx.x < NT / 32) ? red[threadIdx.x] : 0.f;
#pragma unroll
        for (int o = 16; o; o >>= 1) s += __shfl_xor_sync(0xffffffffu, s, o);
    }
    return s;
}

// ---------------- stage A: i_hat = FFT2(image), s0 ---------------------------
__global__ __launch_bounds__(NT, 1) void kA(const float* __restrict__ img) {
    extern __shared__ float2 sc[];
    __shared__ float s_twr[128], s_twi[128];
    __shared__ float red[NT / 32];
    int b = blockIdx.x;
    int tid = threadIdx.x;
    INIT_TWIDDLES();

    float local = 0.f;
    for (int idx = tid; idx < 16384; idx += NT) {
        float v = img[b * 16384 + idx];
        int r = idx >> 7, c = idx & 127;
        sc[r * NPAD + c] = make_float2(v, 0.f);
        local += v;
    }
    float s = block_sum(local, red);   // includes the barrier before FFT
    if (tid == 0) g_s0[b] = s * (1.f / 16384.f);
    __syncthreads();

    r8_stage<false, 0>(sc, s_twr, s_twi);
    comb_stage<false, 0>(sc, s_twr, s_twi);
    r8_stage<false, 1>(sc, s_twr, s_twi);
    comb_stage<false, 1>(sc, s_twr, s_twi);

    for (int idx = tid; idx < 16384; idx += NT) {
        int r = idx >> 7, c = idx & 127;
        g_ihat[b * 16384 + idx] = sc[r * NPAD + c];
    }
}

// ---------------- stage B: u1 = |ifft2(i_hat*psi)|, s1 partial, u1_hat -------
__global__ __launch_bounds__(NT, 1) void kB() {
    extern __shared__ float2 sc[];
    __shared__ float s_twr[128], s_twi[128];
    __shared__ float red[NT / 32];
    int bi = blockIdx.x;              // b*16 + j1*4 + l1
    int b  = bi >> 4;
    int j1 = (bi >> 2) & 3;
    int tid = threadIdx.x;
    INIT_TWIDDLES();
    __syncthreads();

    const float2* src = g_ihat + (size_t)b * 16384;
    const float*  psi = g_psi + ((size_t)bi & 15) * 16384 + ((size_t)0);
    const float*  psi1 = g_psi + (((size_t)(bi & 15)) << 14);

    pass_load_inv0(sc, src, psi1, s_twr, s_twi);        // inv dim0: comb
    r8_stage<true, 0>(sc, s_twr, s_twi);                // inv dim0: r8
    comb_stage<true, 1>(sc, s_twr, s_twi);              // inv dim1: comb
    float local = pass_inv1_r8_mag<true>(sc, s_twr, s_twi);  // inv dim1: r8 + mag
    float s = block_sum(local, red);
    if (tid == 0) g_s1part[bi] = s;
    __syncthreads();

    if (j1 < 3) {                     // j1 == 3 never consumed by second order
        r8_stage<false, 0>(sc, s_twr, s_twi);
        comb_stage<false, 0>(sc, s_twr, s_twi);
        r8_stage<false, 1>(sc, s_twr, s_twi);
        pass_fwd1_store(sc, g_u1hat + (size_t)bi * 16384, s_twr, s_twi);
    }
}

// ---------------- stage C: s2 partial = sum |ifft2(u1_hat*psi_j2)| -----------
__global__ __launch_bounds__(NT, 1) void kC() {
    extern __shared__ float2 sc[];
    __shared__ float s_twr[128], s_twi[128];
    __shared__ float red[NT / 32];
    int bi = blockIdx.x;              // b*96 + pair*16 + l1*4 + l2
    int b    = bi / 96;
    int r96  = bi % 96;
    int pair = r96 >> 4;
    int l1   = (r96 >> 2) & 3;
    int l2   = r96 & 3;
    const int J1[6] = {0, 0, 0, 1, 1, 2};
    const int J2[6] = {1, 2, 3, 2, 3, 3};
    int j1 = J1[pair], j2 = J2[pair];
    int tid = threadIdx.x;
    INIT_TWIDDLES();
    __syncthreads();

    const float2* src = g_u1hat + (((size_t)b * 16 + j1 * 4 + l1) << 14);
    const float*  psi = g_psi + (((size_t)j2 * 4 + l2) << 14);

    pass_load_inv0(sc, src, psi, s_twr, s_twi);         // inv dim0: comb
    r8_stage<true, 0>(sc, s_twr, s_twi);                // inv dim0: r8
    comb_stage<true, 1>(sc, s_twr, s_twi);              // inv dim1: comb
    float local = pass_inv1_r8_mag<false>(sc, s_twr, s_twi); // inv dim1: r8+mag, no write
    float s = block_sum(local, red);
    if (tid == 0) g_s2part[bi] = s;
}

// ---------------- stage D: deterministic reduce + MLP ------------------------
__global__ void kD(const float* __restrict__ fc1w, const float* __restrict__ fc1b,
                   const float* __restrict__ fc2w, const float* __restrict__ fc2b,
                   float* __restrict__ out) {
    int b = threadIdx.x;
    if (b >= 64) return;
    float s[11];
    s[0] = g_s0[b];
    for (int j = 0; j < 4; j++) {
        float acc = 0.f;
        for (int l = 0; l < 4; l++) acc += g_s1part[b * 16 + j * 4 + l];
        s[1 + j] = acc * (1.f / (4.f * 16384.f));
    }
    for (int p = 0; p < 6; p++) {
        float acc = 0.f;
        for (int k = 0; k < 16; k++) acc += g_s2part[b * 96 + p * 16 + k];
        s[5 + p] = acc * (1.f / (16.f * 16384.f));
    }
    float h[4];
    for (int i = 0; i < 4; i++) {
        float a = fc1b[i];
        for (int t = 0; t < 11; t++) a += fc1w[i * 11 + t] * s[t];
        h[i] = fmaxf(a, 0.f);
    }
    for (int k = 0; k < 10; k++) {
        float a = fc2b[k];
        for (int i = 0; i < 4; i++) a += fc2w[k * 4 + i] * h[i];
        out[b * 10 + k] = 1.f / (1.f + expf(-a));
    }
}

// ---------------- launch -----------------------------------------------------
extern "C" void kernel_launch(void* const* d_in, const int* in_sizes, int n_in,
                              void* d_out, int out_size) {
    const float* img  = (const float*)d_in[0];
    const float* fc1w = (const float*)d_in[1];
    const float* fc1b = (const float*)d_in[2];
    const float* fc2w = (const float*)d_in[3];
    const float* fc2b = (const float*)d_in[4];
    float* out = (float*)d_out;

    const size_t smem = 128 * NPAD * sizeof(float2);   // 132096 bytes
    cudaFuncSetAttribute(kA, cudaFuncAttributeMaxDynamicSharedMemorySize, (int)smem);
    cudaFuncSetAttribute(kB, cudaFuncAttributeMaxDynamicSharedMemorySize, (int)smem);
    cudaFuncSetAttribute(kC, cudaFuncAttributeMaxDynamicSharedMemorySize, (int)smem);

    init_psi_kernel<<<256, 1024>>>();
    kA<<<64, NT, smem>>>(img);
    kB<<<1024, NT, smem>>>();
    kC<<<6144, NT, smem>>>();
    kD<<<1, 64>>>(fc1w, fc1b, fc2w, fc2b, out);
}